// round 17
// baseline (speedup 1.0000x reference)
#include <cuda_runtime.h>
#include <math.h>

#define E       1024
#define DH      64
#define MT      128
#define KC      32
#define NCH     32          // E/KC
#define NROWS   32768
#define NTILES  256         // NROWS/MT
#define NBATCH  4

typedef unsigned long long u64;

// ---------------- scratch ----------------
__device__ float g_A[E * 16];                       // fused [k][16] = [Wq@w | Wk@w]
__device__ float g_c16[16];                         // fused feature bias
__device__ float g_qP[NROWS * 16];                  // query features (2 MB)
__device__ float g_Tpart[(size_t)NTILES * 16 * E];  // per-CTA T partials (16.8 MB)
__device__ float g_KPS[NTILES * 16];                // per-CTA kp column sums
__device__ float g_T[NBATCH * 16 * E];              // reduced T [b][f][c]
__device__ float g_S[NBATCH * 16 * DH];             // S [b][f][d]

__device__ __forceinline__ void ffma2(u64& d, u64 a, u64 b) {
    asm("fma.rn.f32x2 %0, %1, %2, %0;" : "+l"(d) : "l"(a), "l"(b));
}

// ---------------- kernel 1: fold A = [Wq@w | Wk@w], bias ----------------
__global__ void prep_kernel(const float* __restrict__ w,
                            const float* __restrict__ Wq, const float* __restrict__ bq,
                            const float* __restrict__ Wk, const float* __restrict__ bk) {
    int idx = blockIdx.x * 256 + threadIdx.x;   // 16384 = 1024*16
    int k = idx >> 4, c = idx & 15;
    const float* W = (c < 8) ? Wq : Wk;
    int cc = c & 7;
    float a = 0.f;
    #pragma unroll 8
    for (int d = 0; d < DH; d++) a += W[k * DH + d] * w[d * 8 + cc];
    g_A[k * 16 + c] = a;
    if (idx < 16) {
        const float* b = (idx < 8) ? bq : bk;
        int c2 = idx & 7;
        float s = 0.f;
        for (int d = 0; d < DH; d++) s += b[d] * w[d * 8 + c2];
        g_c16[idx] = s;
    }
}

// ---------------- kernel 2: p-GEMM + features + T-partials -------------
// smem layout (bytes):
//   [0,16640)      sXT  float[32][130]   (phase1: x chunk, transposed)
//   [16640,20736)  sAd  float2[32][16]   (phase1: A chunk, duplicated {a,a})
//   [0,18432)      sXr  float[128][36]   (phase2 overlay: x chunk, row-major)
//   [20736,29440)  sP   float[128][17]   (p staging)
//   [29440,45824)  sKd  float2[128][16]  (Kp duplicated {kp,kp})
#define XT_OFF 0
#define AD_OFF 16640
#define XR_OFF 0
#define P_OFF  20736
#define KD_OFF 29440
#define SMEM_B 45824

__global__ __launch_bounds__(128) void favor_main(const float* __restrict__ x) {
    static __shared__ __align__(16) unsigned char sm[SMEM_B];
    float*  sXT = (float*)(sm + XT_OFF);
    float2* sAd = (float2*)(sm + AD_OFF);
    float*  sXr = (float*)(sm + XR_OFF);
    float*  sP  = (float*)(sm + P_OFF);
    float2* sKd = (float2*)(sm + KD_OFF);

    const int tid  = threadIdx.x;
    const int row0 = blockIdx.x * MT;

    // ======== phase 1: p[128][16] = x_tile @ A  (thread tile 4 rows x 4 cols)
    const int rq = tid >> 2;   // 0..31  rows 4rq..4rq+3
    const int cq = tid & 3;    // 0..3   cols 4cq..4cq+3
    u64 acc[2][4];
    #pragma unroll
    for (int i = 0; i < 2; i++)
        #pragma unroll
        for (int j = 0; j < 4; j++) acc[i][j] = 0ull;

    for (int ct = 0; ct < NCH; ct++) {
        const int kt = ct * KC;
        // stage x chunk transposed: sXT[kk][row]
        #pragma unroll
        for (int i = 0; i < 8; i++) {
            int u = i * 128 + tid, row = u >> 3, c4 = u & 7;
            float4 v = *(const float4*)(x + (size_t)(row0 + row) * E + kt + c4 * 4);
            sXT[(4 * c4 + 0) * 130 + row] = v.x;
            sXT[(4 * c4 + 1) * 130 + row] = v.y;
            sXT[(4 * c4 + 2) * 130 + row] = v.z;
            sXT[(4 * c4 + 3) * 130 + row] = v.w;
        }
        // stage A chunk duplicated {a,a}
        {
            int kk = tid >> 2, q = tid & 3;
            float4 a4 = *(const float4*)(g_A + (size_t)(kt + kk) * 16 + q * 4);
            sAd[kk * 16 + q * 4 + 0] = make_float2(a4.x, a4.x);
            sAd[kk * 16 + q * 4 + 1] = make_float2(a4.y, a4.y);
            sAd[kk * 16 + q * 4 + 2] = make_float2(a4.z, a4.z);
            sAd[kk * 16 + q * 4 + 3] = make_float2(a4.w, a4.w);
        }
        __syncthreads();
        #pragma unroll 4
        for (int kk = 0; kk < KC; kk++) {
            u64 xa = *(const u64*)&sXT[kk * 130 + 4 * rq];       // rows 4rq,4rq+1
            u64 xb = *(const u64*)&sXT[kk * 130 + 4 * rq + 2];   // rows 4rq+2,4rq+3
            #pragma unroll
            for (int c = 0; c < 4; c++) {
                u64 a = *(const u64*)&sAd[kk * 16 + 4 * cq + c];
                ffma2(acc[0][c], xa, a);
                ffma2(acc[1][c], xb, a);
            }
        }
        __syncthreads();
    }
    // stage p + bias into sP
    #pragma unroll
    for (int rp = 0; rp < 2; rp++)
        #pragma unroll
        for (int c = 0; c < 4; c++) {
            float2 v = *(float2*)&acc[rp][c];
            int col = 4 * cq + c;
            float b = g_c16[col];
            sP[(4 * rq + 2 * rp)     * 17 + col] = v.x + b;
            sP[(4 * rq + 2 * rp + 1) * 17 + col] = v.y + b;
        }
    __syncthreads();

    // ======== features: one row per thread
    {
        const float INV = 0.3535533905932738f;   // 1/sqrt(8)
        float qs[8], qc[8], ks[8], kc[8];
        #pragma unroll
        for (int f = 0; f < 8; f++) sincosf(sP[tid * 17 + f],     &qs[f], &qc[f]);
        #pragma unroll
        for (int f = 0; f < 8; f++) sincosf(sP[tid * 17 + 8 + f], &ks[f], &kc[f]);
        float4* gq = (float4*)(g_qP + (size_t)(row0 + tid) * 16);
        gq[0] = make_float4(qc[0]*INV, qc[1]*INV, qc[2]*INV, qc[3]*INV);
        gq[1] = make_float4(qc[4]*INV, qc[5]*INV, qc[6]*INV, qc[7]*INV);
        gq[2] = make_float4(qs[0]*INV, qs[1]*INV, qs[2]*INV, qs[3]*INV);
        gq[3] = make_float4(qs[4]*INV, qs[5]*INV, qs[6]*INV, qs[7]*INV);
        #pragma unroll
        for (int f = 0; f < 8; f++) {
            float a = kc[f] * INV, b = ks[f] * INV;
            sKd[tid * 16 + f]     = make_float2(a, a);
            sKd[tid * 16 + 8 + f] = make_float2(b, b);
        }
    }
    __syncthreads();

    // ======== per-CTA kp column sums (for v-bias term)
    if (tid < 16) {
        float s = 0.f;
        for (int r = 0; r < MT; r++) s += sKd[r * 16 + tid].x;
        g_KPS[blockIdx.x * 16 + tid] = s;
    }
    __syncthreads();

    // ======== phase 2: T_part[16][1024] = Kp^T @ x_tile
    const int f2 = tid >> 3;   // 0..15 feature
    const int cg = tid & 7;    // 0..7  col group (4 cols)
    for (int ct = 0; ct < NCH; ct++) {
        const int kt = ct * KC;
        // stage x chunk row-major (L2-hot re-read)
        #pragma unroll
        for (int i = 0; i < 8; i++) {
            int u = i * 128 + tid, row = u >> 3, c4 = u & 7;
            float4 v = *(const float4*)(x + (size_t)(row0 + row) * E + kt + c4 * 4);
            *(float4*)&sXr[row * 36 + c4 * 4] = v;
        }
        __syncthreads();
        u64 t0 = 0ull, t1 = 0ull;
        #pragma unroll 4
        for (int r = 0; r < MT; r++) {
            u64 kp = *(const u64*)&sKd[r * 16 + f2];
            u64 x0 = *(const u64*)&sXr[r * 36 + 4 * cg];
            u64 x1 = *(const u64*)&sXr[r * 36 + 4 * cg + 2];
            ffma2(t0, x0, kp);
            ffma2(t1, x1, kp);
        }
        float2 a0 = *(float2*)&t0, a1 = *(float2*)&t1;
        *(float4*)&g_Tpart[(size_t)blockIdx.x * 16 * E + (size_t)f2 * E + kt + 4 * cg] =
            make_float4(a0.x, a0.y, a1.x, a1.y);
        __syncthreads();
    }
}

// ---------------- kernel 3: reduce T partials (64 per batch) -----------
__global__ void reduce_T_kernel() {
    int idx = blockIdx.x * 256 + threadIdx.x;    // 65536 = 4*16*1024
    int b = idx >> 14;
    int fc = idx & 16383;
    const float* src = g_Tpart + (size_t)(b * 64) * 16 * E + fc;
    float s = 0.f;
    #pragma unroll 8
    for (int j = 0; j < 64; j++) s += src[(size_t)j * 16 * E];
    g_T[idx] = s;
}

// ---------------- kernel 4: S = T @ Wv + kpsum x bv --------------------
__global__ void S_kernel(const float* __restrict__ Wv, const float* __restrict__ bv) {
    int idx = blockIdx.x * 256 + threadIdx.x;    // 4096 = 4*16*64
    int b = idx >> 10, f = (idx >> 6) & 15, d = idx & 63;
    float kps = 0.f;
    #pragma unroll 8
    for (int j = 0; j < 64; j++) kps += g_KPS[(b * 64 + j) * 16 + f];
    const float* T = g_T + (size_t)b * 16384 + (size_t)f * 1024;
    float s = 0.f;
    #pragma unroll 8
    for (int c = 0; c < 1024; c++) s += T[c] * Wv[c * DH + d];
    g_S[b * 1024 + f * 64 + d] = s + kps * bv[d];
}

// ---------------- kernel 5: y = qP @ S (4 threads/row) -----------------
__global__ __launch_bounds__(128) void final_kernel(float* __restrict__ out) {
    __shared__ float4 sS[256];    // 16 f x 16 float4 (64 cols)
    int tid = threadIdx.x;
    int row = blockIdx.x * 32 + (tid >> 2);
    int q   = tid & 3;
    int b   = row >> 13;
    sS[tid]       = ((const float4*)(g_S + b * 1024))[tid];
    sS[tid + 128] = ((const float4*)(g_S + b * 1024))[tid + 128];
    __syncthreads();

    float qf[16];
    const float4* qp4 = (const float4*)(g_qP + (size_t)row * 16);
    #pragma unroll
    for (int i = 0; i < 4; i++) {
        float4 v = qp4[i];
        qf[i*4] = v.x; qf[i*4+1] = v.y; qf[i*4+2] = v.z; qf[i*4+3] = v.w;
    }
    float4 o[4];
    #pragma unroll
    for (int j = 0; j < 4; j++) o[j] = make_float4(0.f, 0.f, 0.f, 0.f);
    #pragma unroll
    for (int f = 0; f < 16; f++) {
        float qv = qf[f];
        #pragma unroll
        for (int j = 0; j < 4; j++) {
            float4 sv = sS[f * 16 + q * 4 + j];
            o[j].x += qv * sv.x; o[j].y += qv * sv.y;
            o[j].z += qv * sv.z; o[j].w += qv * sv.w;
        }
    }
    float4* po = (float4*)(out + (size_t)row * 64 + q * 16);
    #pragma unroll
    for (int j = 0; j < 4; j++) po[j] = o[j];
}

// ---------------- launch -----------------------------------------------
extern "C" void kernel_launch(void* const* d_in, const int* in_sizes, int n_in,
                              void* d_out, int out_size) {
    const float* x  = (const float*)d_in[0];
    const float* w  = (const float*)d_in[1];
    const float* Wq = (const float*)d_in[2];
    const float* bq = (const float*)d_in[3];
    const float* Wk = (const float*)d_in[4];
    const float* bk = (const float*)d_in[5];
    const float* Wv = (const float*)d_in[6];
    const float* bv = (const float*)d_in[7];
    float* out = (float*)d_out;

    prep_kernel<<<64, 256>>>(w, Wq, bq, Wk, bk);
    favor_main<<<NTILES, 128>>>(x);
    reduce_T_kernel<<<256, 256>>>();
    S_kernel<<<16, 256>>>(Wv, bv);
    final_kernel<<<1024, 128>>>(out);
}